// round 11
// baseline (speedup 1.0000x reference)
#include <cuda_runtime.h>
#include <cuda_fp16.h>
#include <cstdint>

#define NTHREADS 1024
#define TILE_M   32
#define NGROUPS  4

// half-element strides (conflict-free ldmatrix / stores)
#define SW2 264   // W2h [128][256+pad]
#define SW1 136   // W1h [48][128+pad]
#define SA   56   // A1h [32][48+pad]
#define SHH 136   // Hh  [32][128+pad]

// smem byte offsets
#define OFF_W2   0              // 128*264*2 = 67584
#define OFF_W1   67584          // 48*136*2  = 13056
#define OFF_GRP  80640          // per-group region base
#define G_A1     0              // 3584 B
#define G_H      3584           // 8704 B
#define G_PS     12288          // 2048 B
#define GRP_SZ   14336
#define OFF_CN   137984         // 992 floats = 3968 B
#define SMEM_BYTES 141952

// CN float offsets
#define C_L1G 0
#define C_L1B 48
#define C_B1  96
#define C_B2  224
#define C_G2  480
#define C_BB2 736

__device__ __forceinline__ unsigned su32(const void* p) {
    return (unsigned)__cvta_generic_to_shared(p);
}

// tanh-based GELU: HW tanh.approx; error << fp16 rounding of H
__device__ __forceinline__ float gelu_fast(float x) {
    float u = 0.7978845608028654f * fmaf(0.044715f * x, x * x, x);
    float t;
    asm("tanh.approx.f32 %0, %1;" : "=f"(t) : "f"(u));
    return 0.5f * x * (1.0f + t);
}

__device__ __forceinline__ float2 shfl_xor_f2(float2 v, int m) {
    float2 r;
    r.x = __shfl_xor_sync(0xffffffffu, v.x, m);
    r.y = __shfl_xor_sync(0xffffffffu, v.y, m);
    return r;
}

#define LDM_X4(R, addr)                                                        \
    asm volatile("ldmatrix.sync.aligned.m8n8.x4.shared.b16 {%0,%1,%2,%3}, [%4];" \
        : "=r"((R)[0]), "=r"((R)[1]), "=r"((R)[2]), "=r"((R)[3]) : "r"(addr))

#define LDM_X4T(R, addr)                                                       \
    asm volatile("ldmatrix.sync.aligned.m8n8.x4.trans.shared.b16 {%0,%1,%2,%3}, [%4];" \
        : "=r"((R)[0]), "=r"((R)[1]), "=r"((R)[2]), "=r"((R)[3]) : "r"(addr))

#define MMA_F16(C, A, b0, b1)                                                  \
    asm volatile("mma.sync.aligned.m16n8k16.row.col.f32.f16.f16.f32 "          \
        "{%0,%1,%2,%3}, {%4,%5,%6,%7}, {%8,%9}, {%0,%1,%2,%3};"                \
        : "+f"((C)[0]), "+f"((C)[1]), "+f"((C)[2]), "+f"((C)[3])               \
        : "r"((A)[0]), "r"((A)[1]), "r"((A)[2]), "r"((A)[3]), "r"(b0), "r"(b1))

// group-scoped barrier: 256 threads, ids 1..4
#define BARG(id) asm volatile("bar.sync %0, 256;" :: "r"(id) : "memory")

__global__ void __launch_bounds__(NTHREADS, 1)
pose_mlp_kernel(const float* __restrict__ pose,
                const float* __restrict__ ln1g, const float* __restrict__ ln1b,
                const float* __restrict__ w1,   const float* __restrict__ b1,
                const float* __restrict__ w2,   const float* __restrict__ b2,
                const float* __restrict__ ln2g, const float* __restrict__ ln2b,
                float* __restrict__ out, int ntiles)
{
    extern __shared__ char smem[];
    __half* W2h = (__half*)(smem + OFF_W2);
    __half* W1h = (__half*)(smem + OFF_W1);
    float*  CN  = (float*)(smem + OFF_CN);

    const int tid  = threadIdx.x;
    const int lane = tid & 31;
    const int warp = tid >> 5;
    const int gr   = warp >> 3;           // pipeline group 0..3
    const int wc   = warp & 7;            // warp col (8), Wr = 1
    const int tid2 = tid & 255;           // thread within group
    const int g    = lane >> 2;
    const int t4   = lane & 3;
    const int bid  = gr + 1;              // named barrier id

    char* gbase = smem + OFF_GRP + gr * GRP_SZ;
    __half* A1h = (__half*)(gbase + G_A1);
    __half* Hh  = (__half*)(gbase + G_H);
    float2* PS  = (float2*)(gbase + G_PS);

    const int lm_m  = lane >> 3;
    const int lm_r  = lane & 7;
    const int a_row = lm_r + (lm_m & 1) * 8;
    const int a_kof = (lm_m >> 1) * 8;
    const int b_kof = lm_r + (lm_m & 1) * 8;
    const int b_cof = (lm_m >> 1) * 8;

    // LN1: 8 threads per row (within group), 6 cols each
    const int ln_r  = tid2 >> 3;
    const int ln_c0 = (tid2 & 7) * 6;

    // ---- one-time: weights + consts -> smem (whole CTA) ----
    for (int i = tid; i < 8192; i += NTHREADS) {            // W2 via float4
        int k = i >> 6;
        int c = (i & 63) << 2;
        float4 v = reinterpret_cast<const float4*>(w2)[i];
        __half2* d = (__half2*)&W2h[k * SW2 + c];
        d[0] = __floats2half2_rn(v.x, v.y);
        d[1] = __floats2half2_rn(v.z, v.w);
    }
    for (int i = tid; i < 48 * 128; i += NTHREADS) {        // W1, rows 45..47 zero
        int k = i >> 7;
        int c = i & 127;
        W1h[k * SW1 + c] = (k < 45) ? __float2half_rn(w1[k * 128 + c])
                                    : __float2half_rn(0.0f);
    }
    if (tid < 48) {
        CN[C_L1G + tid] = (tid < 45) ? ln1g[tid] : 0.0f;
        CN[C_L1B + tid] = (tid < 45) ? ln1b[tid] : 0.0f;
    }
    if (tid < 128) CN[C_B1 + tid] = b1[tid];
    if (tid >= 128 && tid < 384) {
        int i = tid - 128;
        CN[C_B2 + i] = b2[i]; CN[C_G2 + i] = ln2g[i]; CN[C_BB2 + i] = ln2b[i];
    }
    __syncthreads();   // only CTA-wide barrier; groups independent after this

    const int stride = NGROUPS * gridDim.x;
    int tile = blockIdx.x * NGROUPS + gr;

    // ---- prologue LN1 (gmem -> A1h) ----
    if (tile < ntiles) {
        const float* row = pose + ((size_t)tile * TILE_M + ln_r) * 45;
        float x[6]; float s = 0.f, q = 0.f;
        #pragma unroll
        for (int j = 0; j < 6; j++) {
            int c = ln_c0 + j;
            x[j] = (c < 45) ? row[c] : 0.f;
            s += x[j]; q += x[j] * x[j];
        }
        #pragma unroll
        for (int off = 1; off <= 4; off <<= 1) {
            s += __shfl_xor_sync(0xffffffffu, s, off);
            q += __shfl_xor_sync(0xffffffffu, q, off);
        }
        float mu   = s * (1.0f / 45.0f);
        float var  = q * (1.0f / 45.0f) - mu * mu;
        float rstd = rsqrtf(fmaxf(var, 0.f) + 1e-5f);
        __half2* dstp = (__half2*)&A1h[ln_r * SA + ln_c0];
        #pragma unroll
        for (int j2 = 0; j2 < 3; j2++) {
            int c = ln_c0 + 2 * j2;
            float y0 = (x[2*j2]   - mu) * rstd * CN[C_L1G + c]     + CN[C_L1B + c];
            float y1 = (x[2*j2+1] - mu) * rstd * CN[C_L1G + c + 1] + CN[C_L1B + c + 1];
            dstp[j2] = __floats2half2_rn(y0, y1);
        }
    }

    for (; tile < ntiles; tile += stride) {
        const int tn = tile + stride;
        BARG(bid);   // A1h ready

        // ---- GEMM1: [32x48] x [48x128], 16 cols/warp (bias folded) ----
        float acc1[2][2][4];
        #pragma unroll
        for (int n = 0; n < 2; n++) {
            float2 bv = *reinterpret_cast<const float2*>(&CN[C_B1 + wc * 16 + n * 8 + 2 * t4]);
            #pragma unroll
            for (int mi = 0; mi < 2; mi++) {
                acc1[mi][n][0] = bv.x; acc1[mi][n][1] = bv.y;
                acc1[mi][n][2] = bv.x; acc1[mi][n][3] = bv.y;
            }
        }
        {
            unsigned ab = su32(A1h) + (a_row * SA + a_kof) * 2;
            unsigned bb = su32(W1h) + (b_kof * SW1 + wc * 16 + b_cof) * 2;
            #pragma unroll
            for (int kk = 0; kk < 3; kk++) {
                unsigned a[2][4], b[4];
                LDM_X4(a[0], ab + (kk * 16) * 2);
                LDM_X4(a[1], ab + (16 * SA + kk * 16) * 2);
                LDM_X4T(b, bb + (kk * 16 * SW1) * 2);
                #pragma unroll
                for (int n = 0; n < 2; n++) {
                    MMA_F16(acc1[0][n], a[0], b[n * 2], b[n * 2 + 1]);
                    MMA_F16(acc1[1][n], a[1], b[n * 2], b[n * 2 + 1]);
                }
            }
        }

        // ---- epilogue1: fast GELU -> fp16 H ----
        #pragma unroll
        for (int mi = 0; mi < 2; mi++) {
            int r = mi * 16 + g;
            #pragma unroll
            for (int n = 0; n < 2; n++) {
                int c = wc * 16 + n * 8 + 2 * t4;
                *(__half2*)&Hh[r * SHH + c] =
                    __floats2half2_rn(gelu_fast(acc1[mi][n][0]), gelu_fast(acc1[mi][n][1]));
                *(__half2*)&Hh[(r + 8) * SHH + c] =
                    __floats2half2_rn(gelu_fast(acc1[mi][n][2]), gelu_fast(acc1[mi][n][3]));
            }
        }
        BARG(bid);   // Hh ready

        // ---- GEMM2: [32x128] x [128x256], 32 cols/warp (bias folded) ----
        float acc2[2][4][4];
        #pragma unroll
        for (int n = 0; n < 4; n++) {
            float2 bv = *reinterpret_cast<const float2*>(&CN[C_B2 + wc * 32 + n * 8 + 2 * t4]);
            #pragma unroll
            for (int mi = 0; mi < 2; mi++) {
                acc2[mi][n][0] = bv.x; acc2[mi][n][1] = bv.y;
                acc2[mi][n][2] = bv.x; acc2[mi][n][3] = bv.y;
            }
        }
        {
            unsigned ab = su32(Hh)  + (a_row * SHH + a_kof) * 2;
            unsigned bb = su32(W2h) + (b_kof * SW2 + wc * 32 + b_cof) * 2;
            #pragma unroll 4
            for (int kk = 0; kk < 8; kk++) {
                unsigned a[2][4], b[2][4];
                LDM_X4(a[0], ab + (kk * 16) * 2);
                LDM_X4(a[1], ab + (16 * SHH + kk * 16) * 2);
                LDM_X4T(b[0], bb + (kk * 16 * SW2) * 2);
                LDM_X4T(b[1], bb + (kk * 16 * SW2 + 16) * 2);
                #pragma unroll
                for (int n = 0; n < 4; n++) {
                    int pp = n >> 1, qf = (n & 1) * 2;
                    MMA_F16(acc2[0][n], a[0], b[pp][qf], b[pp][qf + 1]);
                    MMA_F16(acc2[1][n], a[1], b[pp][qf], b[pp][qf + 1]);
                }
            }
        }

        // ---- LN2 partial sums (reduce over t4, stash per warp-col) ----
        #pragma unroll
        for (int mi = 0; mi < 2; mi++) {
            float s0 = 0.f, q0 = 0.f, s1 = 0.f, q1 = 0.f;
            #pragma unroll
            for (int n = 0; n < 4; n++) {
                float a0 = acc2[mi][n][0], a1 = acc2[mi][n][1];
                float a2 = acc2[mi][n][2], a3 = acc2[mi][n][3];
                s0 += a0 + a1; q0 += a0 * a0 + a1 * a1;
                s1 += a2 + a3; q1 += a2 * a2 + a3 * a3;
            }
            #pragma unroll
            for (int off = 1; off <= 2; off <<= 1) {
                s0 += __shfl_xor_sync(0xffffffffu, s0, off);
                q0 += __shfl_xor_sync(0xffffffffu, q0, off);
                s1 += __shfl_xor_sync(0xffffffffu, s1, off);
                q1 += __shfl_xor_sync(0xffffffffu, q1, off);
            }
            if (t4 == 0) {
                int r = mi * 16 + g;
                PS[r * 8 + wc]       = make_float2(s0, q0);
                PS[(r + 8) * 8 + wc] = make_float2(s1, q1);
            }
        }
        BARG(bid);   // PS ready

        // ---- epilogue2: quad-transpose -> coalesced STG.128 ----
        // After transpose, lane t4 owns cols [cb, cb+8) of row r (same row across quad).
        float* outp = out + (size_t)tile * TILE_M * 256;
        const int cb = wc * 32 + t4 * 8;
        const float4 gA = *reinterpret_cast<const float4*>(&CN[C_G2 + cb]);
        const float4 gB = *reinterpret_cast<const float4*>(&CN[C_G2 + cb + 4]);
        const float4 bA = *reinterpret_cast<const float4*>(&CN[C_BB2 + cb]);
        const float4 bB = *reinterpret_cast<const float4*>(&CN[C_BB2 + cb + 4]);
        const bool p0 = (t4 & 1);
        const bool p1 = (t4 & 2);
        #pragma unroll
        for (int mi = 0; mi < 2; mi++) {
            #pragma unroll
            for (int h = 0; h < 2; h++) {
                int r = mi * 16 + g + h * 8;
                float s = 0.f, q = 0.f;
                #pragma unroll
                for (int pc = 0; pc < 8; pc++) {
                    float2 pv = PS[r * 8 + pc];
                    s += pv.x; q += pv.y;
                }
                float mu   = s * (1.0f / 256.0f);
                float var  = q * (1.0f / 256.0f) - mu * mu;
                float rstd = rsqrtf(fmaxf(var, 0.f) + 1e-5f);

                // chunks: c[n] = cols n*8 + 2*t4 of row r
                float2 c0 = make_float2(acc2[mi][0][h*2], acc2[mi][0][h*2+1]);
                float2 c1 = make_float2(acc2[mi][1][h*2], acc2[mi][1][h*2+1]);
                float2 c2 = make_float2(acc2[mi][2][h*2], acc2[mi][2][h*2+1]);
                float2 c3 = make_float2(acc2[mi][3][h*2], acc2[mi][3][h*2+1]);

                // stage A: swap n0 <-> t0 (bfly xor 1)
                float2 ta = p0 ? c0 : c1;
                ta = shfl_xor_f2(ta, 1);
                c0 = p0 ? ta : c0;  c1 = p0 ? c1 : ta;
                float2 tb = p0 ? c2 : c3;
                tb = shfl_xor_f2(tb, 1);
                c2 = p0 ? tb : c2;  c3 = p0 ? c3 : tb;
                // stage B: swap n1 <-> t1 (bfly xor 2)
                ta = p1 ? c0 : c2;
                ta = shfl_xor_f2(ta, 2);
                c0 = p1 ? ta : c0;  c2 = p1 ? c2 : ta;
                tb = p1 ? c1 : c3;
                tb = shfl_xor_f2(tb, 2);
                c1 = p1 ? tb : c1;  c3 = p1 ? c3 : tb;
                // now lane t4 holds cols cb..cb+8 of row r: c0.x c0.y c1.x c1.y c2.x c2.y c3.x c3.y

                float4 o1, o2;
                o1.x = (c0.x - mu) * rstd * gA.x + bA.x;
                o1.y = (c0.y - mu) * rstd * gA.y + bA.y;
                o1.z = (c1.x - mu) * rstd * gA.z + bA.z;
                o1.w = (c1.y - mu) * rstd * gA.w + bA.w;
                o2.x = (c2.x - mu) * rstd * gB.x + bB.x;
                o2.y = (c2.y - mu) * rstd * gB.y + bB.y;
                o2.z = (c3.x - mu) * rstd * gB.z + bB.z;
                o2.w = (c3.y - mu) * rstd * gB.w + bB.w;
                *reinterpret_cast<float4*>(&outp[(size_t)r * 256 + cb])     = o1;
                *reinterpret_cast<float4*>(&outp[(size_t)r * 256 + cb + 4]) = o2;
            }
        }

        // ---- LN1 for next tile (overlaps STGs above) ----
        if (tn < ntiles) {
            const float* row = pose + ((size_t)tn * TILE_M + ln_r) * 45;
            float x[6]; float s = 0.f, q = 0.f;
            #pragma unroll
            for (int j = 0; j < 6; j++) {
                int c = ln_c0 + j;
                x[j] = (c < 45) ? row[c] : 0.f;
                s += x[j]; q += x[j] * x[j];
            }
            #pragma unroll
            for (int off = 1; off <= 4; off <<= 1) {
                s += __shfl_xor_sync(0xffffffffu, s, off);
                q += __shfl_xor_sync(0xffffffffu, q, off);
            }
            float mu   = s * (1.0f / 45.0f);
            float var  = q * (1.0f / 45.0f) - mu * mu;
            float rstd = rsqrtf(fmaxf(var, 0.f) + 1e-5f);
            __half2* dstp = (__half2*)&A1h[ln_r * SA + ln_c0];
            #pragma unroll
            for (int j2 = 0; j2 < 3; j2++) {
                int c = ln_c0 + 2 * j2;
                float y0 = (x[2*j2]   - mu) * rstd * CN[C_L1G + c]     + CN[C_L1B + c];
                float y1 = (x[2*j2+1] - mu) * rstd * CN[C_L1G + c + 1] + CN[C_L1B + c + 1];
                dstp[j2] = __floats2half2_rn(y0, y1);
            }
        }
    }
}

extern "C" void kernel_launch(void* const* d_in, const int* in_sizes, int n_in,
                              void* d_out, int out_size)
{
    const float* pose = (const float*)d_in[0];
    const float* ln1g = (const float*)d_in[1];
    const float* ln1b = (const float*)d_in[2];
    const float* w1   = (const float*)d_in[3];
    const float* b1   = (const float*)d_in[4];
    const float* w2   = (const float*)d_in[5];
    const float* b2   = (const float*)d_in[6];
    const float* ln2g = (const float*)d_in[7];
    const float* ln2b = (const float*)d_in[8];
    float* out = (float*)d_out;

    int nrows  = in_sizes[0] / 45;
    int ntiles = nrows / TILE_M;

    int dev = 0;
    cudaGetDevice(&dev);
    int nsm = 148;
    cudaDeviceGetAttribute(&nsm, cudaDevAttrMultiProcessorCount, dev);

    cudaFuncSetAttribute(pose_mlp_kernel,
                         cudaFuncAttributeMaxDynamicSharedMemorySize, SMEM_BYTES);

    int grid = nsm;
    int need = (ntiles + NGROUPS - 1) / NGROUPS;
    if (grid > need) grid = need;
    pose_mlp_kernel<<<grid, NTHREADS, SMEM_BYTES>>>(
        pose, ln1g, ln1b, w1, b1, w2, b2, ln2g, ln2b, out, ntiles);
}

// round 13
// speedup vs baseline: 1.0360x; 1.0360x over previous
#include <cuda_runtime.h>
#include <cuda_fp16.h>
#include <cstdint>

#define NTHREADS 1024
#define TILE_M   32
#define NGROUPS  4

// half-element strides (conflict-free ldmatrix / stores)
#define SW2 264   // W2h [128][256+pad]
#define SW1 136   // W1h [48][128+pad]
#define SA   56   // A1h [32][48+pad]
#define SHH 136   // Hh  [32][128+pad]

// smem byte offsets
#define OFF_W2   0              // 128*264*2 = 67584
#define OFF_W1   67584          // 48*136*2  = 13056
#define OFF_GRP  80640          // per-group region base
#define G_A1     0              // 2 x 3584 B (double-buffered)
#define G_H      7168           // 8704 B
#define G_PS     15872          // 2048 B
#define GRP_SZ   17920
#define OFF_CN   152320         // 992 floats = 3968 B
#define SMEM_BYTES 156288

// CN float offsets
#define C_L1G 0
#define C_L1B 48
#define C_B1  96
#define C_B2  224
#define C_G2  480
#define C_BB2 736

__device__ __forceinline__ unsigned su32(const void* p) {
    return (unsigned)__cvta_generic_to_shared(p);
}

// tanh-based GELU: HW tanh.approx; error << fp16 rounding of H
__device__ __forceinline__ float gelu_fast(float x) {
    float u = 0.7978845608028654f * fmaf(0.044715f * x, x * x, x);
    float t;
    asm("tanh.approx.f32 %0, %1;" : "=f"(t) : "f"(u));
    return 0.5f * x * (1.0f + t);
}

#define LDM_X4(R, addr)                                                        \
    asm volatile("ldmatrix.sync.aligned.m8n8.x4.shared.b16 {%0,%1,%2,%3}, [%4];" \
        : "=r"((R)[0]), "=r"((R)[1]), "=r"((R)[2]), "=r"((R)[3]) : "r"(addr))

#define LDM_X4T(R, addr)                                                       \
    asm volatile("ldmatrix.sync.aligned.m8n8.x4.trans.shared.b16 {%0,%1,%2,%3}, [%4];" \
        : "=r"((R)[0]), "=r"((R)[1]), "=r"((R)[2]), "=r"((R)[3]) : "r"(addr))

#define MMA_F16(C, A, b0, b1)                                                  \
    asm volatile("mma.sync.aligned.m16n8k16.row.col.f32.f16.f16.f32 "          \
        "{%0,%1,%2,%3}, {%4,%5,%6,%7}, {%8,%9}, {%0,%1,%2,%3};"                \
        : "+f"((C)[0]), "+f"((C)[1]), "+f"((C)[2]), "+f"((C)[3])               \
        : "r"((A)[0]), "r"((A)[1]), "r"((A)[2]), "r"((A)[3]), "r"(b0), "r"(b1))

// group-scoped barrier: 256 threads, ids 1..4
#define BARG(id) asm volatile("bar.sync %0, 256;" :: "r"(id) : "memory")

__global__ void __launch_bounds__(NTHREADS, 1)
pose_mlp_kernel(const float* __restrict__ pose,
                const float* __restrict__ ln1g, const float* __restrict__ ln1b,
                const float* __restrict__ w1,   const float* __restrict__ b1,
                const float* __restrict__ w2,   const float* __restrict__ b2,
                const float* __restrict__ ln2g, const float* __restrict__ ln2b,
                float* __restrict__ out, int ntiles)
{
    extern __shared__ char smem[];
    __half* W2h = (__half*)(smem + OFF_W2);
    __half* W1h = (__half*)(smem + OFF_W1);
    float*  CN  = (float*)(smem + OFF_CN);

    const int tid  = threadIdx.x;
    const int lane = tid & 31;
    const int warp = tid >> 5;
    const int gr   = warp >> 3;           // pipeline group 0..3
    const int wc   = warp & 7;            // warp col (8), Wr = 1
    const int tid2 = tid & 255;           // thread within group
    const int g    = lane >> 2;
    const int t4   = lane & 3;
    const int bid  = gr + 1;              // named barrier id

    char* gbase = smem + OFF_GRP + gr * GRP_SZ;
    __half* A1b0 = (__half*)(gbase + G_A1);
    __half* A1b1 = (__half*)(gbase + G_A1 + 3584);
    __half* Hh   = (__half*)(gbase + G_H);
    float2* PS   = (float2*)(gbase + G_PS);

    const int lm_m  = lane >> 3;
    const int lm_r  = lane & 7;
    const int a_row = lm_r + (lm_m & 1) * 8;
    const int a_kof = (lm_m >> 1) * 8;
    const int b_kof = lm_r + (lm_m & 1) * 8;
    const int b_cof = (lm_m >> 1) * 8;

    // LN1: 8 threads per row (within group), 6 cols each
    const int ln_r  = tid2 >> 3;
    const int ln_c0 = (tid2 & 7) * 6;

    // ---- one-time: weights + consts -> smem (whole CTA) ----
    for (int i = tid; i < 8192; i += NTHREADS) {            // W2 via float4
        int k = i >> 6;
        int c = (i & 63) << 2;
        float4 v = reinterpret_cast<const float4*>(w2)[i];
        __half2* d = (__half2*)&W2h[k * SW2 + c];
        d[0] = __floats2half2_rn(v.x, v.y);
        d[1] = __floats2half2_rn(v.z, v.w);
    }
    for (int i = tid; i < 48 * 128; i += NTHREADS) {        // W1, rows 45..47 zero
        int k = i >> 7;
        int c = i & 127;
        W1h[k * SW1 + c] = (k < 45) ? __float2half_rn(w1[k * 128 + c])
                                    : __float2half_rn(0.0f);
    }
    if (tid < 48) {
        CN[C_L1G + tid] = (tid < 45) ? ln1g[tid] : 0.0f;
        CN[C_L1B + tid] = (tid < 45) ? ln1b[tid] : 0.0f;
    }
    if (tid < 128) CN[C_B1 + tid] = b1[tid];
    if (tid >= 128 && tid < 384) {
        int i = tid - 128;
        CN[C_B2 + i] = b2[i]; CN[C_G2 + i] = ln2g[i]; CN[C_BB2 + i] = ln2b[i];
    }
    __syncthreads();   // only CTA-wide barrier; groups independent after this

    const int stride = NGROUPS * gridDim.x;
    int tile = blockIdx.x * NGROUPS + gr;

    // ---- prologue LN1 (gmem -> A1 buf0) ----
    if (tile < ntiles) {
        const float* row = pose + ((size_t)tile * TILE_M + ln_r) * 45;
        float x[6]; float s = 0.f, q = 0.f;
        #pragma unroll
        for (int j = 0; j < 6; j++) {
            int c = ln_c0 + j;
            x[j] = (c < 45) ? row[c] : 0.f;
            s += x[j]; q += x[j] * x[j];
        }
        #pragma unroll
        for (int off = 1; off <= 4; off <<= 1) {
            s += __shfl_xor_sync(0xffffffffu, s, off);
            q += __shfl_xor_sync(0xffffffffu, q, off);
        }
        float mu   = s * (1.0f / 45.0f);
        float var  = q * (1.0f / 45.0f) - mu * mu;
        float rstd = rsqrtf(fmaxf(var, 0.f) + 1e-5f);
        __half2* dstp = (__half2*)&A1b0[ln_r * SA + ln_c0];
        #pragma unroll
        for (int j2 = 0; j2 < 3; j2++) {
            int c = ln_c0 + 2 * j2;
            float y0 = (x[2*j2]   - mu) * rstd * CN[C_L1G + c]     + CN[C_L1B + c];
            float y1 = (x[2*j2+1] - mu) * rstd * CN[C_L1G + c + 1] + CN[C_L1B + c + 1];
            dstp[j2] = __floats2half2_rn(y0, y1);
        }
    }
    BARG(bid);   // A1 buf0 ready

    int p = 0;
    for (; tile < ntiles; tile += stride, p ^= 1) {
        const int tn = tile + stride;
        __half* A1cur = p ? A1b1 : A1b0;
        __half* A1nxt = p ? A1b0 : A1b1;

        // ---- GEMM1: [32x48] x [48x128], 16 cols/warp (bias folded) ----
        float acc1[2][2][4];
        #pragma unroll
        for (int n = 0; n < 2; n++) {
            float2 bv = *reinterpret_cast<const float2*>(&CN[C_B1 + wc * 16 + n * 8 + 2 * t4]);
            #pragma unroll
            for (int mi = 0; mi < 2; mi++) {
                acc1[mi][n][0] = bv.x; acc1[mi][n][1] = bv.y;
                acc1[mi][n][2] = bv.x; acc1[mi][n][3] = bv.y;
            }
        }
        {
            unsigned ab = su32(A1cur) + (a_row * SA + a_kof) * 2;
            unsigned bb = su32(W1h) + (b_kof * SW1 + wc * 16 + b_cof) * 2;
            #pragma unroll
            for (int kk = 0; kk < 3; kk++) {
                unsigned a[2][4], b[4];
                LDM_X4(a[0], ab + (kk * 16) * 2);
                LDM_X4(a[1], ab + (16 * SA + kk * 16) * 2);
                LDM_X4T(b, bb + (kk * 16 * SW1) * 2);
                #pragma unroll
                for (int n = 0; n < 2; n++) {
                    MMA_F16(acc1[0][n], a[0], b[n * 2], b[n * 2 + 1]);
                    MMA_F16(acc1[1][n], a[1], b[n * 2], b[n * 2 + 1]);
                }
            }
        }

        // ---- epilogue1: fast GELU -> fp16 H ----
        #pragma unroll
        for (int mi = 0; mi < 2; mi++) {
            int r = mi * 16 + g;
            #pragma unroll
            for (int n = 0; n < 2; n++) {
                int c = wc * 16 + n * 8 + 2 * t4;
                *(__half2*)&Hh[r * SHH + c] =
                    __floats2half2_rn(gelu_fast(acc1[mi][n][0]), gelu_fast(acc1[mi][n][1]));
                *(__half2*)&Hh[(r + 8) * SHH + c] =
                    __floats2half2_rn(gelu_fast(acc1[mi][n][2]), gelu_fast(acc1[mi][n][3]));
            }
        }
        BARG(bid);   // Hh ready

        // ---- GEMM2: [32x128] x [128x256], 32 cols/warp (bias folded) ----
        float acc2[2][4][4];
        #pragma unroll
        for (int n = 0; n < 4; n++) {
            float2 bv = *reinterpret_cast<const float2*>(&CN[C_B2 + wc * 32 + n * 8 + 2 * t4]);
            #pragma unroll
            for (int mi = 0; mi < 2; mi++) {
                acc2[mi][n][0] = bv.x; acc2[mi][n][1] = bv.y;
                acc2[mi][n][2] = bv.x; acc2[mi][n][3] = bv.y;
            }
        }
        {
            unsigned ab = su32(Hh)  + (a_row * SHH + a_kof) * 2;
            unsigned bb = su32(W2h) + (b_kof * SW2 + wc * 32 + b_cof) * 2;
            #pragma unroll 4
            for (int kk = 0; kk < 8; kk++) {
                unsigned a[2][4], b[2][4];
                LDM_X4(a[0], ab + (kk * 16) * 2);
                LDM_X4(a[1], ab + (16 * SHH + kk * 16) * 2);
                LDM_X4T(b[0], bb + (kk * 16 * SW2) * 2);
                LDM_X4T(b[1], bb + (kk * 16 * SW2 + 16) * 2);
                #pragma unroll
                for (int n = 0; n < 4; n++) {
                    int pp = n >> 1, qf = (n & 1) * 2;
                    MMA_F16(acc2[0][n], a[0], b[pp][qf], b[pp][qf + 1]);
                    MMA_F16(acc2[1][n], a[1], b[pp][qf], b[pp][qf + 1]);
                }
            }
        }

        // ---- issue next tile's LN1 gmem loads (drain under LN2 sums + barrier) ----
        float x[6];
        if (tn < ntiles) {
            const float* row = pose + ((size_t)tn * TILE_M + ln_r) * 45;
            #pragma unroll
            for (int j = 0; j < 6; j++) {
                int c = ln_c0 + j;
                x[j] = (c < 45) ? row[c] : 0.f;
            }
        }

        // ---- LN2 partial sums (reduce over t4, stash per warp-col) ----
        #pragma unroll
        for (int mi = 0; mi < 2; mi++) {
            float s0 = 0.f, q0 = 0.f, s1 = 0.f, q1 = 0.f;
            #pragma unroll
            for (int n = 0; n < 4; n++) {
                float a0 = acc2[mi][n][0], a1 = acc2[mi][n][1];
                float a2 = acc2[mi][n][2], a3 = acc2[mi][n][3];
                s0 += a0 + a1; q0 += a0 * a0 + a1 * a1;
                s1 += a2 + a3; q1 += a2 * a2 + a3 * a3;
            }
            #pragma unroll
            for (int off = 1; off <= 2; off <<= 1) {
                s0 += __shfl_xor_sync(0xffffffffu, s0, off);
                q0 += __shfl_xor_sync(0xffffffffu, q0, off);
                s1 += __shfl_xor_sync(0xffffffffu, s1, off);
                q1 += __shfl_xor_sync(0xffffffffu, q1, off);
            }
            if (t4 == 0) {
                int r = mi * 16 + g;
                PS[r * 8 + wc]       = make_float2(s0, q0);
                PS[(r + 8) * 8 + wc] = make_float2(s1, q1);
            }
        }

        // ---- finalize next tile's LN1 -> A1nxt (before the barrier) ----
        if (tn < ntiles) {
            float s = 0.f, q = 0.f;
            #pragma unroll
            for (int j = 0; j < 6; j++) { s += x[j]; q += x[j] * x[j]; }
            #pragma unroll
            for (int off = 1; off <= 4; off <<= 1) {
                s += __shfl_xor_sync(0xffffffffu, s, off);
                q += __shfl_xor_sync(0xffffffffu, q, off);
            }
            float mu   = s * (1.0f / 45.0f);
            float var  = q * (1.0f / 45.0f) - mu * mu;
            float rstd = rsqrtf(fmaxf(var, 0.f) + 1e-5f);
            __half2* dstp = (__half2*)&A1nxt[ln_r * SA + ln_c0];
            #pragma unroll
            for (int j2 = 0; j2 < 3; j2++) {
                int c = ln_c0 + 2 * j2;
                float y0 = (x[2*j2]   - mu) * rstd * CN[C_L1G + c]     + CN[C_L1B + c];
                float y1 = (x[2*j2+1] - mu) * rstd * CN[C_L1G + c + 1] + CN[C_L1B + c + 1];
                dstp[j2] = __floats2half2_rn(y0, y1);
            }
        }
        BARG(bid);   // PS ready + A1nxt ready; Hh reads done

        // ---- epilogue2: finalize LN2, store out (overlaps next GEMM1) ----
        float* outp = out + (size_t)tile * TILE_M * 256;
        float mu_[4], rs_[4];
        #pragma unroll
        for (int mi = 0; mi < 2; mi++) {
            #pragma unroll
            for (int h = 0; h < 2; h++) {
                int r = mi * 16 + g + h * 8;
                float s = 0.f, q = 0.f;
                #pragma unroll
                for (int pc = 0; pc < 8; pc++) {
                    float2 pv = PS[r * 8 + pc];
                    s += pv.x; q += pv.y;
                }
                float mu  = s * (1.0f / 256.0f);
                float var = q * (1.0f / 256.0f) - mu * mu;
                mu_[mi * 2 + h] = mu;
                rs_[mi * 2 + h] = rsqrtf(fmaxf(var, 0.f) + 1e-5f);
            }
        }
        #pragma unroll
        for (int n = 0; n < 4; n++) {
            int c = wc * 32 + n * 8 + 2 * t4;
            float2 gv = *reinterpret_cast<const float2*>(&CN[C_G2 + c]);
            float2 bv = *reinterpret_cast<const float2*>(&CN[C_BB2 + c]);
            #pragma unroll
            for (int mi = 0; mi < 2; mi++) {
                #pragma unroll
                for (int h = 0; h < 2; h++) {
                    int r = mi * 16 + g + h * 8;
                    float mu = mu_[mi * 2 + h], rstd = rs_[mi * 2 + h];
                    float v0 = acc2[mi][n][h * 2 + 0];
                    float v1 = acc2[mi][n][h * 2 + 1];
                    float2 o;
                    o.x = (v0 - mu) * rstd * gv.x + bv.x;
                    o.y = (v1 - mu) * rstd * gv.y + bv.y;
                    *reinterpret_cast<float2*>(&outp[(size_t)r * 256 + c]) = o;
                }
            }
        }
        // NOTE: PS is read above AFTER the barrier; next tile's writes to PS
        // occur only after the next "Hh ready" barrier, so no WAR hazard.
    }
}

extern "C" void kernel_launch(void* const* d_in, const int* in_sizes, int n_in,
                              void* d_out, int out_size)
{
    const float* pose = (const float*)d_in[0];
    const float* ln1g = (const float*)d_in[1];
    const float* ln1b = (const float*)d_in[2];
    const float* w1   = (const float*)d_in[3];
    const float* b1   = (const float*)d_in[4];
    const float* w2   = (const float*)d_in[5];
    const float* b2   = (const float*)d_in[6];
    const float* ln2g = (const float*)d_in[7];
    const float* ln2b = (const float*)d_in[8];
    float* out = (float*)d_out;

    int nrows  = in_sizes[0] / 45;
    int ntiles = nrows / TILE_M;

    int dev = 0;
    cudaGetDevice(&dev);
    int nsm = 148;
    cudaDeviceGetAttribute(&nsm, cudaDevAttrMultiProcessorCount, dev);

    cudaFuncSetAttribute(pose_mlp_kernel,
                         cudaFuncAttributeMaxDynamicSharedMemorySize, SMEM_BYTES);

    int grid = nsm;
    int need = (ntiles + NGROUPS - 1) / NGROUPS;
    if (grid > need) grid = need;
    pose_mlp_kernel<<<grid, NTHREADS, SMEM_BYTES>>>(
        pose, ln1g, ln1b, w1, b1, w2, b2, ln2g, ln2b, out, ntiles);
}

// round 14
// speedup vs baseline: 1.0520x; 1.0154x over previous
#include <cuda_runtime.h>
#include <cuda_fp16.h>
#include <cstdint>

#define NTHREADS 1024
#define TILE_M   32
#define NGROUPS  4

// half-element strides (conflict-free ldmatrix / stores)
#define SW2 264   // W2h [128][256+pad]
#define SW1 136   // W1h [48][128+pad]
#define SA   56   // A1h [32][48+pad]
#define SHH 136   // Hh  [32][128+pad]

// smem byte offsets
#define OFF_W2   0              // 128*264*2 = 67584
#define OFF_W1   67584          // 48*136*2  = 13056
#define OFF_GRP  80640          // per-group region base
#define G_A1     0              // 3584 B
#define G_H      3584           // 8704 B
#define G_PS     12288          // 2048 B
#define GRP_SZ   14336
#define OFF_CN   137984         // 992 floats = 3968 B
#define SMEM_BYTES 141952

// CN float offsets
#define C_L1G 0
#define C_L1B 48
#define C_B1  96
#define C_B2  224
#define C_G2  480
#define C_BB2 736

__device__ __forceinline__ unsigned su32(const void* p) {
    return (unsigned)__cvta_generic_to_shared(p);
}

// tanh-based GELU: HW tanh.approx; error << fp16 rounding of H
__device__ __forceinline__ float gelu_fast(float x) {
    float u = 0.7978845608028654f * fmaf(0.044715f * x, x * x, x);
    float t;
    asm("tanh.approx.f32 %0, %1;" : "=f"(t) : "f"(u));
    return 0.5f * x * (1.0f + t);
}

#define LDM_X4(R, addr)                                                        \
    asm volatile("ldmatrix.sync.aligned.m8n8.x4.shared.b16 {%0,%1,%2,%3}, [%4];" \
        : "=r"((R)[0]), "=r"((R)[1]), "=r"((R)[2]), "=r"((R)[3]) : "r"(addr))

#define LDM_X4T(R, addr)                                                       \
    asm volatile("ldmatrix.sync.aligned.m8n8.x4.trans.shared.b16 {%0,%1,%2,%3}, [%4];" \
        : "=r"((R)[0]), "=r"((R)[1]), "=r"((R)[2]), "=r"((R)[3]) : "r"(addr))

#define MMA_F16(C, A, b0, b1)                                                  \
    asm volatile("mma.sync.aligned.m16n8k16.row.col.f32.f16.f16.f32 "          \
        "{%0,%1,%2,%3}, {%4,%5,%6,%7}, {%8,%9}, {%0,%1,%2,%3};"                \
        : "+f"((C)[0]), "+f"((C)[1]), "+f"((C)[2]), "+f"((C)[3])               \
        : "r"((A)[0]), "r"((A)[1]), "r"((A)[2]), "r"((A)[3]), "r"(b0), "r"(b1))

// group-scoped barrier: 256 threads, ids 1..4
#define BARG(id) asm volatile("bar.sync %0, 256;" :: "r"(id) : "memory")

__global__ void __launch_bounds__(NTHREADS, 1)
pose_mlp_kernel(const float* __restrict__ pose,
                const float* __restrict__ ln1g, const float* __restrict__ ln1b,
                const float* __restrict__ w1,   const float* __restrict__ b1,
                const float* __restrict__ w2,   const float* __restrict__ b2,
                const float* __restrict__ ln2g, const float* __restrict__ ln2b,
                float* __restrict__ out, int ntiles)
{
    extern __shared__ char smem[];
    __half* W2h = (__half*)(smem + OFF_W2);
    __half* W1h = (__half*)(smem + OFF_W1);
    float*  CN  = (float*)(smem + OFF_CN);

    const int tid  = threadIdx.x;
    const int lane = tid & 31;
    const int warp = tid >> 5;
    const int gr   = warp >> 3;           // pipeline group 0..3
    const int wc   = warp & 7;            // warp col (8), Wr = 1
    const int tid2 = tid & 255;           // thread within group
    const int g    = lane >> 2;
    const int t4   = lane & 3;
    const int bid  = gr + 1;              // named barrier id

    char* gbase = smem + OFF_GRP + gr * GRP_SZ;
    __half* A1h = (__half*)(gbase + G_A1);
    __half* Hh  = (__half*)(gbase + G_H);
    float2* PS  = (float2*)(gbase + G_PS);
    const float4* PS4 = (const float4*)(gbase + G_PS);

    const int lm_m  = lane >> 3;
    const int lm_r  = lane & 7;
    const int a_row = lm_r + (lm_m & 1) * 8;
    const int a_kof = (lm_m >> 1) * 8;
    const int b_kof = lm_r + (lm_m & 1) * 8;
    const int b_cof = (lm_m >> 1) * 8;

    // LN1: 8 threads per row (within group), 6 cols each
    const int ln_r  = tid2 >> 3;
    const int ln_c0 = (tid2 & 7) * 6;

    // ---- one-time: weights + consts -> smem (whole CTA) ----
    for (int i = tid; i < 8192; i += NTHREADS) {            // W2 via float4
        int k = i >> 6;
        int c = (i & 63) << 2;
        float4 v = reinterpret_cast<const float4*>(w2)[i];
        __half2* d = (__half2*)&W2h[k * SW2 + c];
        d[0] = __floats2half2_rn(v.x, v.y);
        d[1] = __floats2half2_rn(v.z, v.w);
    }
    for (int i = tid; i < 48 * 128; i += NTHREADS) {        // W1, rows 45..47 zero
        int k = i >> 7;
        int c = i & 127;
        W1h[k * SW1 + c] = (k < 45) ? __float2half_rn(w1[k * 128 + c])
                                    : __float2half_rn(0.0f);
    }
    if (tid < 48) {
        CN[C_L1G + tid] = (tid < 45) ? ln1g[tid] : 0.0f;
        CN[C_L1B + tid] = (tid < 45) ? ln1b[tid] : 0.0f;
    }
    if (tid < 128) CN[C_B1 + tid] = b1[tid];
    if (tid >= 128 && tid < 384) {
        int i = tid - 128;
        CN[C_B2 + i] = b2[i]; CN[C_G2 + i] = ln2g[i]; CN[C_BB2 + i] = ln2b[i];
    }
    __syncthreads();   // only CTA-wide barrier; groups independent after this

    const int stride = NGROUPS * gridDim.x;
    int tile = blockIdx.x * NGROUPS + gr;

    // ---- prologue LN1 (gmem -> A1h) ----
    if (tile < ntiles) {
        const float* row = pose + ((size_t)tile * TILE_M + ln_r) * 45;
        float x[6]; float s = 0.f, q = 0.f;
        #pragma unroll
        for (int j = 0; j < 6; j++) {
            int c = ln_c0 + j;
            x[j] = (c < 45) ? row[c] : 0.f;
            s += x[j]; q += x[j] * x[j];
        }
        #pragma unroll
        for (int off = 1; off <= 4; off <<= 1) {
            s += __shfl_xor_sync(0xffffffffu, s, off);
            q += __shfl_xor_sync(0xffffffffu, q, off);
        }
        float mu   = s * (1.0f / 45.0f);
        float var  = q * (1.0f / 45.0f) - mu * mu;
        float rstd = rsqrtf(fmaxf(var, 0.f) + 1e-5f);
        __half2* dstp = (__half2*)&A1h[ln_r * SA + ln_c0];
        #pragma unroll
        for (int j2 = 0; j2 < 3; j2++) {
            int c = ln_c0 + 2 * j2;
            float y0 = (x[2*j2]   - mu) * rstd * CN[C_L1G + c]     + CN[C_L1B + c];
            float y1 = (x[2*j2+1] - mu) * rstd * CN[C_L1G + c + 1] + CN[C_L1B + c + 1];
            dstp[j2] = __floats2half2_rn(y0, y1);
        }
    }

    for (; tile < ntiles; tile += stride) {
        const int tn = tile + stride;
        BARG(bid);   // A1h ready

        // ---- GEMM1: [32x48] x [48x128], 16 cols/warp (bias folded) ----
        float acc1[2][2][4];
        #pragma unroll
        for (int n = 0; n < 2; n++) {
            float2 bv = *reinterpret_cast<const float2*>(&CN[C_B1 + wc * 16 + n * 8 + 2 * t4]);
            #pragma unroll
            for (int mi = 0; mi < 2; mi++) {
                acc1[mi][n][0] = bv.x; acc1[mi][n][1] = bv.y;
                acc1[mi][n][2] = bv.x; acc1[mi][n][3] = bv.y;
            }
        }
        {
            unsigned ab = su32(A1h) + (a_row * SA + a_kof) * 2;
            unsigned bb = su32(W1h) + (b_kof * SW1 + wc * 16 + b_cof) * 2;
            #pragma unroll
            for (int kk = 0; kk < 3; kk++) {
                unsigned a[2][4], b[4];
                LDM_X4(a[0], ab + (kk * 16) * 2);
                LDM_X4(a[1], ab + (16 * SA + kk * 16) * 2);
                LDM_X4T(b, bb + (kk * 16 * SW1) * 2);
                #pragma unroll
                for (int n = 0; n < 2; n++) {
                    MMA_F16(acc1[0][n], a[0], b[n * 2], b[n * 2 + 1]);
                    MMA_F16(acc1[1][n], a[1], b[n * 2], b[n * 2 + 1]);
                }
            }
        }

        // ---- epilogue1: fast GELU -> fp16 H ----
        #pragma unroll
        for (int mi = 0; mi < 2; mi++) {
            int r = mi * 16 + g;
            #pragma unroll
            for (int n = 0; n < 2; n++) {
                int c = wc * 16 + n * 8 + 2 * t4;
                *(__half2*)&Hh[r * SHH + c] =
                    __floats2half2_rn(gelu_fast(acc1[mi][n][0]), gelu_fast(acc1[mi][n][1]));
                *(__half2*)&Hh[(r + 8) * SHH + c] =
                    __floats2half2_rn(gelu_fast(acc1[mi][n][2]), gelu_fast(acc1[mi][n][3]));
            }
        }
        BARG(bid);   // Hh ready

        // ---- GEMM2: [32x128] x [128x256], 32 cols/warp (bias folded) ----
        float acc2[2][4][4];
        #pragma unroll
        for (int n = 0; n < 4; n++) {
            float2 bv = *reinterpret_cast<const float2*>(&CN[C_B2 + wc * 32 + n * 8 + 2 * t4]);
            #pragma unroll
            for (int mi = 0; mi < 2; mi++) {
                acc2[mi][n][0] = bv.x; acc2[mi][n][1] = bv.y;
                acc2[mi][n][2] = bv.x; acc2[mi][n][3] = bv.y;
            }
        }
        {
            unsigned ab = su32(Hh)  + (a_row * SHH + a_kof) * 2;
            unsigned bb = su32(W2h) + (b_kof * SW2 + wc * 32 + b_cof) * 2;
            #pragma unroll 4
            for (int kk = 0; kk < 8; kk++) {
                unsigned a[2][4], b[2][4];
                LDM_X4(a[0], ab + (kk * 16) * 2);
                LDM_X4(a[1], ab + (16 * SHH + kk * 16) * 2);
                LDM_X4T(b[0], bb + (kk * 16 * SW2) * 2);
                LDM_X4T(b[1], bb + (kk * 16 * SW2 + 16) * 2);
                #pragma unroll
                for (int n = 0; n < 4; n++) {
                    int pp = n >> 1, qf = (n & 1) * 2;
                    MMA_F16(acc2[0][n], a[0], b[pp][qf], b[pp][qf + 1]);
                    MMA_F16(acc2[1][n], a[1], b[pp][qf], b[pp][qf + 1]);
                }
            }
        }

        // ---- LN2 partial sums (reduce over t4, stash per warp-col) ----
        #pragma unroll
        for (int mi = 0; mi < 2; mi++) {
            float s0 = 0.f, q0 = 0.f, s1 = 0.f, q1 = 0.f;
            #pragma unroll
            for (int n = 0; n < 4; n++) {
                float a0 = acc2[mi][n][0], a1 = acc2[mi][n][1];
                float a2 = acc2[mi][n][2], a3 = acc2[mi][n][3];
                s0 += a0 + a1; q0 += a0 * a0 + a1 * a1;
                s1 += a2 + a3; q1 += a2 * a2 + a3 * a3;
            }
            #pragma unroll
            for (int off = 1; off <= 2; off <<= 1) {
                s0 += __shfl_xor_sync(0xffffffffu, s0, off);
                q0 += __shfl_xor_sync(0xffffffffu, q0, off);
                s1 += __shfl_xor_sync(0xffffffffu, s1, off);
                q1 += __shfl_xor_sync(0xffffffffu, q1, off);
            }
            if (t4 == 0) {
                int r = mi * 16 + g;
                PS[r * 8 + wc]       = make_float2(s0, q0);
                PS[(r + 8) * 8 + wc] = make_float2(s1, q1);
            }
        }
        BARG(bid);   // PS ready

        // ---- epilogue2: mu/rstd via float4 PS reads, streaming stores ----
        float* outp = out + (size_t)tile * TILE_M * 256;
        float mu_[4], rs_[4];
        #pragma unroll
        for (int mi = 0; mi < 2; mi++) {
            #pragma unroll
            for (int h = 0; h < 2; h++) {
                int r = mi * 16 + g + h * 8;
                float s = 0.f, q = 0.f;
                #pragma unroll
                for (int pc4 = 0; pc4 < 4; pc4++) {
                    float4 v = PS4[r * 4 + pc4];     // two (s,q) partials
                    s += v.x + v.z; q += v.y + v.w;
                }
                float mu  = s * (1.0f / 256.0f);
                float var = q * (1.0f / 256.0f) - mu * mu;
                mu_[mi * 2 + h] = mu;
                rs_[mi * 2 + h] = rsqrtf(fmaxf(var, 0.f) + 1e-5f);
            }
        }
        #pragma unroll
        for (int n = 0; n < 4; n++) {
            int c = wc * 32 + n * 8 + 2 * t4;
            float2 gv = *reinterpret_cast<const float2*>(&CN[C_G2 + c]);
            float2 bv = *reinterpret_cast<const float2*>(&CN[C_BB2 + c]);
            #pragma unroll
            for (int mi = 0; mi < 2; mi++) {
                #pragma unroll
                for (int h = 0; h < 2; h++) {
                    int r = mi * 16 + g + h * 8;
                    float mu = mu_[mi * 2 + h], rstd = rs_[mi * 2 + h];
                    float v0 = acc2[mi][n][h * 2 + 0];
                    float v1 = acc2[mi][n][h * 2 + 1];
                    float2 o;
                    o.x = (v0 - mu) * rstd * gv.x + bv.x;
                    o.y = (v1 - mu) * rstd * gv.y + bv.y;
                    __stcs(reinterpret_cast<float2*>(&outp[(size_t)r * 256 + c]), o);
                }
            }
        }

        // ---- LN1 for next tile (overlaps STGs above) ----
        if (tn < ntiles) {
            const float* row = pose + ((size_t)tn * TILE_M + ln_r) * 45;
            float x[6]; float s = 0.f, q = 0.f;
            #pragma unroll
            for (int j = 0; j < 6; j++) {
                int c = ln_c0 + j;
                x[j] = (c < 45) ? row[c] : 0.f;
                s += x[j]; q += x[j] * x[j];
            }
            #pragma unroll
            for (int off = 1; off <= 4; off <<= 1) {
                s += __shfl_xor_sync(0xffffffffu, s, off);
                q += __shfl_xor_sync(0xffffffffu, q, off);
            }
            float mu   = s * (1.0f / 45.0f);
            float var  = q * (1.0f / 45.0f) - mu * mu;
            float rstd = rsqrtf(fmaxf(var, 0.f) + 1e-5f);
            __half2* dstp = (__half2*)&A1h[ln_r * SA + ln_c0];
            #pragma unroll
            for (int j2 = 0; j2 < 3; j2++) {
                int c = ln_c0 + 2 * j2;
                float y0 = (x[2*j2]   - mu) * rstd * CN[C_L1G + c]     + CN[C_L1B + c];
                float y1 = (x[2*j2+1] - mu) * rstd * CN[C_L1G + c + 1] + CN[C_L1B + c + 1];
                dstp[j2] = __floats2half2_rn(y0, y1);
            }
        }
    }
}

extern "C" void kernel_launch(void* const* d_in, const int* in_sizes, int n_in,
                              void* d_out, int out_size)
{
    const float* pose = (const float*)d_in[0];
    const float* ln1g = (const float*)d_in[1];
    const float* ln1b = (const float*)d_in[2];
    const float* w1   = (const float*)d_in[3];
    const float* b1   = (const float*)d_in[4];
    const float* w2   = (const float*)d_in[5];
    const float* b2   = (const float*)d_in[6];
    const float* ln2g = (const float*)d_in[7];
    const float* ln2b = (const float*)d_in[8];
    float* out = (float*)d_out;

    int nrows  = in_sizes[0] / 45;
    int ntiles = nrows / TILE_M;

    int dev = 0;
    cudaGetDevice(&dev);
    int nsm = 148;
    cudaDeviceGetAttribute(&nsm, cudaDevAttrMultiProcessorCount, dev);

    cudaFuncSetAttribute(pose_mlp_kernel,
                         cudaFuncAttributeMaxDynamicSharedMemorySize, SMEM_BYTES);

    int grid = nsm;
    int need = (ntiles + NGROUPS - 1) / NGROUPS;
    if (grid > need) grid = need;
    pose_mlp_kernel<<<grid, NTHREADS, SMEM_BYTES>>>(
        pose, ln1g, ln1b, w1, b1, w2, b2, ln2g, ln2b, out, ntiles);
}